// round 14
// baseline (speedup 1.0000x reference)
#include <cuda_runtime.h>
#include <cuda_fp16.h>
#include <cstdint>

// Problem shapes (fixed by the dataset)
#define B_ 16
#define N_ 512
#define C_ 384
#define K_ 64
#define NN_ (N_*N_)

// Scratch (no allocs allowed -> __device__ globals)
__device__ float g_attn[B_*K_];
__device__ __half g_tm16[(size_t)B_*NN_];    // tm   [B][512][512] fp16
__device__ __half g_xT16[(size_t)B_*C_*N_];  // xT   [B][C][N]    fp16
__device__ __half g_y16[(size_t)B_*N_*C_];   // y    [B*N][C]     fp16
__device__ __half g_W16[C_*C_];              // W    [C][C]       fp16
__device__ int    g_flag[64];                // gemm1 rowblock completion

__device__ __forceinline__ uint32_t smem_u32(const void* p) {
    uint32_t a;
    asm("{ .reg .u64 t; cvta.to.shared.u64 t, %1; cvt.u32.u64 %0, t; }"
        : "=r"(a) : "l"(p));
    return a;
}
__device__ __forceinline__ void cp_async16(uint32_t dst, const void* src) {
    asm volatile("cp.async.cg.shared.global [%0], [%1], 16;"
                 :: "r"(dst), "l"(src) : "memory");
}
__device__ __forceinline__ void cp_commit() {
    asm volatile("cp.async.commit_group;" ::: "memory");
}
template <int NMax>
__device__ __forceinline__ void cp_wait() {
    asm volatile("cp.async.wait_group %0;" :: "n"(NMax) : "memory");
}
__device__ __forceinline__ void ldsm_x4(uint32_t* r, uint32_t addr) {
    asm volatile("ldmatrix.sync.aligned.m8n8.x4.shared.b16 {%0,%1,%2,%3}, [%4];"
        : "=r"(r[0]), "=r"(r[1]), "=r"(r[2]), "=r"(r[3]) : "r"(addr));
}
__device__ __forceinline__ void ldsm_x4_t(uint32_t* r, uint32_t addr) {
    asm volatile("ldmatrix.sync.aligned.m8n8.x4.trans.shared.b16 {%0,%1,%2,%3}, [%4];"
        : "=r"(r[0]), "=r"(r[1]), "=r"(r[2]), "=r"(r[3]) : "r"(addr));
}
__device__ __forceinline__ void mma_fp16(float* c, const uint32_t* a, const uint32_t* b) {
    asm volatile(
        "mma.sync.aligned.m16n8k16.row.col.f32.f16.f16.f32 "
        "{%0,%1,%2,%3}, {%4,%5,%6,%7}, {%8,%9}, {%0,%1,%2,%3};"
        : "+f"(c[0]), "+f"(c[1]), "+f"(c[2]), "+f"(c[3])
        : "r"(a[0]), "r"(a[1]), "r"(a[2]), "r"(a[3]), "r"(b[0]), "r"(b[1]));
}
__device__ __forceinline__ uint32_t pack_h2(float a, float b) {
    __half2 h = __floats2half2_rn(a, b);
    return *(uint32_t*)&h;
}

// ---------------------------------------------------------------------------
// Node 1: transpose_x(+fp16) + W fp16 + fused pool+attn (self-pooling blocks).
// grid (16, 12, 17), block (32,8):
//   z<16           : transpose slice of batch z
//   z==16, blk<16  : pool + attn for batch blk
//   z==16, blk>=16 : W conversion (176 blocks, strided)
// ---------------------------------------------------------------------------
__global__ void convert_attn_kernel(const float* __restrict__ x,
                                    const float* __restrict__ W,
                                    const float* __restrict__ centers) {
    if (blockIdx.z == 16) {
        int blk = blockIdx.y * 16 + blockIdx.x;       // 0..191
        int t = threadIdx.y * 32 + threadIdx.x;       // 0..255
        if (blk < 16) {
            // ---- fused pool + attn for batch b ----
            int b = blk;
            __shared__ float s_part[2][C_];
            __shared__ float s_q[C_];
            __shared__ float s_red[256];
            __shared__ float s_logit[K_];
            __shared__ float s_mx, s_den;

            const float* xb = x + (size_t)b * N_ * C_;
            for (int task = t; task < 2 * C_; task += 256) {
                int c = task % C_, h = task / C_;
                const float* xp = xb + (size_t)h * 256 * C_ + c;
                float s = 0.f;
                #pragma unroll 8
                for (int n = 0; n < 256; n++) s += xp[(size_t)n * C_];
                s_part[h][c] = s;
            }
            __syncthreads();

            float part = 0.f;
            for (int c = t; c < C_; c += 256) {
                float q = (s_part[0][c] + s_part[1][c]) * (1.0f / N_);
                s_q[c] = q;
                part += q * q;
            }
            s_red[t] = part;
            __syncthreads();
            for (int st = 128; st > 0; st >>= 1) {
                if (t < st) s_red[t] += s_red[t + st];
                __syncthreads();
            }
            float qnorm = sqrtf(s_red[0]);

            if (t < K_) {
                float dot = 0.f, cs = 0.f;
                #pragma unroll 4
                for (int c = 0; c < C_; c++) {
                    float w = centers[(size_t)c * K_ + t];
                    dot += s_q[c] * w;
                    cs  += w * w;
                }
                float denom = fmaxf(qnorm, 1e-12f) * fmaxf(sqrtf(cs), 1e-12f);
                s_logit[t] = dot / denom;
            }
            __syncthreads();
            if (t == 0) {
                float mx = -1e30f;
                for (int k = 0; k < K_; k++) mx = fmaxf(mx, s_logit[k]);
                float den = 0.f;
                for (int k = 0; k < K_; k++) den += expf(s_logit[k] - mx);
                s_mx = mx; s_den = den;
            }
            __syncthreads();
            if (t < K_) g_attn[b * K_ + t] = expf(s_logit[t] - s_mx) / s_den;
            return;
        }
        // ---- W conversion ----
        for (int i = (blk - 16) * 256 + t; i < C_ * C_; i += 176 * 256)
            g_W16[i] = __float2half_rn(W[i]);
        return;
    }
    // ---- transpose slice ----
    __shared__ float tbuf[32][33];
    int b = blockIdx.z;
    int n0 = blockIdx.x * 32, c0 = blockIdx.y * 32;
    int tx = threadIdx.x, ty = threadIdx.y;   // 32 x 8
    #pragma unroll
    for (int i = 0; i < 4; i++)
        tbuf[ty + i * 8][tx] = x[(size_t)b * N_ * C_ + (size_t)(n0 + ty + i * 8) * C_ + c0 + tx];
    __syncthreads();
    #pragma unroll
    for (int i = 0; i < 4; i++) {
        float v = tbuf[tx][ty + i * 8];
        size_t o = (size_t)b * C_ * N_ + (size_t)(c0 + ty + i * 8) * N_ + n0 + tx;
        g_xT16[o] = __float2half_rn(v);
    }
}

// ---------------------------------------------------------------------------
// Node 2: tm via tensor cores (unchanged) + resets g_flag for node 3.
// ---------------------------------------------------------------------------
__global__ __launch_bounds__(256)
void tm_tc_kernel(const float* __restrict__ tran) {
    __shared__ __align__(16) __half s_tr[64 * 128];   // 16KB, swizzled
    __shared__ __align__(16) __half s_at[16 * 64];    // 2KB,  swizzled

    const int tid = threadIdx.x;
    const int warp = tid >> 5, lane = tid & 31;
    const int g = lane >> 2, t4 = lane & 3;
    const int nm0 = blockIdx.x * 128;

    if (blockIdx.x == 0 && tid < 64) g_flag[tid] = 0;   // reset for node 3

    {
        int b = tid >> 4, kq = tid & 15;
        float4 av = *(const float4*)(g_attn + b * 64 + kq * 4);
        uint2 hv;
        hv.x = pack_h2(av.x, av.y);
        hv.y = pack_h2(av.z, av.w);
        int chunk = kq >> 1;
        int base = b * 64 + ((chunk ^ (b & 7)) << 3) + (kq & 1) * 4;
        *(uint2*)(s_at + base) = hv;
    }

    #pragma unroll
    for (int i = 0; i < 8; i++) {
        int f = tid + 256 * i;
        int k = f >> 5, c4 = f & 31;
        float4 v = *(const float4*)(tran + (size_t)k * NN_ + nm0 + c4 * 4);
        uint2 hv;
        hv.x = pack_h2(v.x, v.y);
        hv.y = pack_h2(v.z, v.w);
        int chunk = c4 >> 1;
        int base = k * 128 + ((chunk ^ (k & 7)) << 3) + (c4 & 1) * 4;
        *(uint2*)(s_tr + base) = hv;
    }
    __syncthreads();

    const uint32_t at_base = smem_u32(s_at);
    uint32_t a[4][4];
    {
        int sub = lane >> 3;
        int br = ((sub & 1) << 3) + (lane & 7);
        #pragma unroll
        for (int kc = 0; kc < 4; kc++) {
            int ch16 = kc * 2 + (sub >> 1);
            uint32_t ad = at_base + br * 128 + ((ch16 ^ (br & 7)) << 4);
            ldsm_x4(a[kc], ad);
        }
    }

    const uint32_t tr_base = smem_u32(s_tr);
    float acc[2][4] = {{0.f,0.f,0.f,0.f},{0.f,0.f,0.f,0.f}};
    {
        int sub = lane >> 3;
        int krow_off = ((sub & 1) << 3) + (lane & 7);
        int nch8 = warp * 2 + (sub >> 1);
        #pragma unroll
        for (int kc = 0; kc < 4; kc++) {
            int k = kc * 16 + krow_off;
            uint32_t bd = tr_base + k * 256 + ((nch8 ^ (k & 7)) << 4);
            uint32_t bt[4];
            ldsm_x4_t(bt, bd);
            mma_fp16(acc[0], a[kc], &bt[0]);
            mma_fp16(acc[1], a[kc], &bt[2]);
        }
    }

    uint32_t* out = (uint32_t*)g_tm16;
    #pragma unroll
    for (int n8 = 0; n8 < 2; n8++) {
        int col = nm0 + warp * 16 + n8 * 8 + 2 * t4;
        out[((size_t)g * NN_ + col) >> 1]       = pack_h2(acc[n8][0], acc[n8][1]);
        out[((size_t)(g + 8) * NN_ + col) >> 1] = pack_h2(acc[n8][2], acc[n8][3]);
    }
}

// ---------------------------------------------------------------------------
// fp16 GEMM body (shared by both halves of the fused node).
// CTA 128x64x32, 8 warps (4m x 2n), warp tile 32x32, 3-stage cp.async.
// ---------------------------------------------------------------------------
#define TBM 128
#define TBN 64
#define TBK 32
#define A_BYTES (TBM*TBK*2)            // 8192
#define B_BYTES (TBN*TBK*2)            // 4096
#define STAGE_BYTES (A_BYTES + B_BYTES)        // 12288
#define NSTAGE 3
#define GSMEM_BYTES (NSTAGE*STAGE_BYTES)       // 36864

template <int EPI>
__device__ __forceinline__ void gemm_body(
    uint32_t smb,
    const __half* __restrict__ Ab, const __half* __restrict__ Bb,
    float* __restrict__ Cf, __half* __restrict__ Ch,
    const float* __restrict__ bias,
    int Kk, int lda, int ldb, int ldc,
    int m0, int n0, size_t cbase) {

    const int tid = threadIdx.x;
    const int warp = tid >> 5, lane = tid & 31;
    const int wm = warp >> 1, wn = warp & 1;
    const int g = lane >> 2, t4 = lane & 3;

    auto issue_copy = [&](int s, int k0) {
        uint32_t st = smb + (uint32_t)s * STAGE_BYTES;
        #pragma unroll
        for (int i = 0; i < 2; i++) {
            int id = tid + 256 * i;
            int r = id >> 2, c = id & 3;
            uint32_t d = st + (uint32_t)(r * 64 + ((c ^ ((r >> 1) & 3)) << 4));
            cp_async16(d, Ab + (size_t)(m0 + r) * lda + k0 + c * 8);
        }
        {
            uint32_t bst = st + A_BYTES;
            int r = tid >> 2, c = tid & 3;
            uint32_t d = bst + (uint32_t)(r * 64 + ((c ^ ((r >> 1) & 3)) << 4));
            cp_async16(d, Bb + (size_t)(n0 + r) * ldb + k0 + c * 8);
        }
    };

    float acc[2][4][4];
    #pragma unroll
    for (int mt = 0; mt < 2; mt++)
        #pragma unroll
        for (int nt = 0; nt < 4; nt++)
            #pragma unroll
            for (int q = 0; q < 4; q++) acc[mt][nt][q] = 0.f;

    const int lrA = lane & 15, lkA = (lane >> 4) & 1;
    int offA[2], qA[2];
    #pragma unroll
    for (int mt = 0; mt < 2; mt++) {
        int r = wm * 32 + mt * 16 + lrA;
        offA[mt] = r * 64;
        qA[mt] = (r >> 1) & 3;
    }
    const int b_ntloc = (lane >> 4) & 1, b_kh = (lane >> 3) & 1;
    int offB[2], qB[2];
    #pragma unroll
    for (int P = 0; P < 2; P++) {
        int r = wn * 32 + P * 16 + b_ntloc * 8 + (lane & 7);
        offB[P] = r * 64;
        qB[P] = (r >> 1) & 3;
    }

    auto compute = [&](int s) {
        uint32_t st = smb + (uint32_t)s * STAGE_BYTES;
        uint32_t bst = st + A_BYTES;
        #pragma unroll
        for (int ks = 0; ks < 2; ks++) {
            uint32_t ah[2][4], bh[2][4];
            #pragma unroll
            for (int mt = 0; mt < 2; mt++)
                ldsm_x4(ah[mt], st + offA[mt] + ((((ks * 2 + lkA) ^ qA[mt])) << 4));
            #pragma unroll
            for (int P = 0; P < 2; P++)
                ldsm_x4(bh[P], bst + offB[P] + ((((ks * 2 + b_kh) ^ qB[P])) << 4));
            #pragma unroll
            for (int mt = 0; mt < 2; mt++)
                #pragma unroll
                for (int nt = 0; nt < 4; nt++)
                    mma_fp16(acc[mt][nt], ah[mt], &bh[nt >> 1][(nt & 1) * 2]);
        }
    };

    const int nch = Kk / TBK;

    #pragma unroll
    for (int p = 0; p < NSTAGE - 1; p++) {
        if (p < nch) issue_copy(p, p * TBK);
        cp_commit();
    }

    for (int ch = 0; ch < nch; ch++) {
        cp_wait<NSTAGE - 2>();
        __syncthreads();
        int nxt = ch + NSTAGE - 1;
        if (nxt < nch) issue_copy(nxt % NSTAGE, nxt * TBK);
        cp_commit();
        compute(ch % NSTAGE);
    }

    #pragma unroll
    for (int mt = 0; mt < 2; mt++) {
        int r0 = m0 + wm * 32 + mt * 16 + g;
        #pragma unroll
        for (int nt = 0; nt < 4; nt++) {
            int col = n0 + wn * 32 + nt * 8 + t4 * 2;
            if (EPI == 0) {
                uint32_t* chp = (uint32_t*)Ch;
                chp[(cbase + (size_t)r0 * ldc + col) >> 1] =
                    pack_h2(acc[mt][nt][0], acc[mt][nt][1]);
                chp[(cbase + (size_t)(r0 + 8) * ldc + col) >> 1] =
                    pack_h2(acc[mt][nt][2], acc[mt][nt][3]);
            } else {
                float b0 = __ldg(bias + col), b1 = __ldg(bias + col + 1);
                float* p0 = Cf + (size_t)r0 * ldc + col;
                float* p1 = Cf + (size_t)(r0 + 8) * ldc + col;
                *(float2*)p0 = make_float2(acc[mt][nt][0] + b0, acc[mt][nt][1] + b1);
                *(float2*)p1 = make_float2(acc[mt][nt][2] + b0, acc[mt][nt][3] + b1);
            }
        }
    }
}

// ---------------------------------------------------------------------------
// Node 3: fused gemm1 + gemm2 with device-side dependency flags.
// blocks 0..383  : gemm1 tiles (y = tm @ x), signal g_flag[b*4+mt]
// blocks 384..767: gemm2 tiles (out = y @ W^T + b), spin on g_flag[rb]==6
// ---------------------------------------------------------------------------
__global__ __launch_bounds__(256, 3)
void gemm_fused(const __half* __restrict__ tm16, const __half* __restrict__ xt16,
                __half* __restrict__ y16, const __half* __restrict__ w16,
                float* __restrict__ out, const float* __restrict__ bias) {
    extern __shared__ char sm[];
    const uint32_t smb = smem_u32(sm);
    const int bid = blockIdx.x;

    if (bid < 384) {
        // gemm1: id = mt + 4*(ct + 6*b)
        int mt = bid & 3;
        int tmp = bid >> 2;
        int ct = tmp % 6, b = tmp / 6;
        int m0 = mt * 128, n0 = ct * 64;
        gemm_body<0>(smb,
                     tm16 + (size_t)b * NN_, xt16 + (size_t)b * C_ * N_,
                     nullptr, y16, nullptr,
                     /*K=*/N_, /*lda=*/N_, /*ldb=*/N_, /*ldc=*/C_,
                     m0, n0, (size_t)b * N_ * C_);
        __syncthreads();
        __threadfence();
        if (threadIdx.x == 0) atomicAdd(&g_flag[b * 4 + mt], 1);
    } else {
        // gemm2: id2 = rb + 64*ct
        int id2 = bid - 384;
        int rb = id2 & 63, ct = id2 >> 6;
        int m0 = rb * 128, n0 = ct * 64;
        if (threadIdx.x == 0) {
            while (((volatile int*)g_flag)[rb] < 6) {}
            __threadfence();
        }
        __syncthreads();
        gemm_body<1>(smb,
                     y16, w16, out, nullptr, bias,
                     /*K=*/C_, /*lda=*/C_, /*ldb=*/C_, /*ldc=*/C_,
                     m0, n0, 0);
    }
}

// ---------------------------------------------------------------------------
extern "C" void kernel_launch(void* const* d_in, const int* in_sizes, int n_in,
                              void* d_out, int out_size) {
    const float* x       = (const float*)d_in[0];  // [B,N,C]
    const float* centers = (const float*)d_in[1];  // [C,K]
    const float* tran_ms = (const float*)d_in[2];  // [K,N,N]
    const float* proj_w  = (const float*)d_in[3];  // [C,C]
    const float* proj_b  = (const float*)d_in[4];  // [C]
    float* out = (float*)d_out;                    // [B,N,C]

    __half *tm16, *xt16, *y16, *w16;
    cudaGetSymbolAddress((void**)&tm16, g_tm16);
    cudaGetSymbolAddress((void**)&xt16, g_xT16);
    cudaGetSymbolAddress((void**)&y16, g_y16);
    cudaGetSymbolAddress((void**)&w16, g_W16);

    cudaFuncSetAttribute(gemm_fused, cudaFuncAttributeMaxDynamicSharedMemorySize,
                         GSMEM_BYTES);

    // Node 1: transpose + W conversion + fused pool/attn
    convert_attn_kernel<<<dim3(N_/32, C_/32, B_ + 1), dim3(32, 8)>>>(
        x, proj_w, centers);

    // Node 2: tm = attn @ tran_ms via tensor cores (also resets g_flag)
    tm_tc_kernel<<<NN_ / 128, 256>>>(tran_ms);

    // Node 3: gemm1 + gemm2 fused (flag-synchronized)
    gemm_fused<<<768, 256, GSMEM_BYTES>>>(tm16, xt16, y16, w16, out, proj_b);
}

// round 15
// speedup vs baseline: 1.2618x; 1.2618x over previous
#include <cuda_runtime.h>
#include <cuda_fp16.h>
#include <cstdint>

// Problem shapes (fixed by the dataset)
#define B_ 16
#define N_ 512
#define C_ 384
#define K_ 64
#define NN_ (N_*N_)

// Scratch (no allocs allowed -> __device__ globals)
__device__ float g_qpart[B_][8][C_];
__device__ float g_attn[B_*K_];
__device__ __half g_tm16[(size_t)B_*NN_];    // tm   [B][512][512] fp16
__device__ __half g_xT16[(size_t)B_*C_*N_];  // xT   [B][C][N]    fp16
__device__ __half g_y16[(size_t)B_*N_*C_];   // y    [B*N][C]     fp16
__device__ __half g_W16[C_*C_];              // W    [C][C]       fp16
__device__ int    g_flag[64];                // gemm1 rowblock completion

__device__ __forceinline__ uint32_t smem_u32(const void* p) {
    uint32_t a;
    asm("{ .reg .u64 t; cvta.to.shared.u64 t, %1; cvt.u32.u64 %0, t; }"
        : "=r"(a) : "l"(p));
    return a;
}
__device__ __forceinline__ void cp_async16(uint32_t dst, const void* src) {
    asm volatile("cp.async.cg.shared.global [%0], [%1], 16;"
                 :: "r"(dst), "l"(src) : "memory");
}
__device__ __forceinline__ void cp_commit() {
    asm volatile("cp.async.commit_group;" ::: "memory");
}
template <int NMax>
__device__ __forceinline__ void cp_wait() {
    asm volatile("cp.async.wait_group %0;" :: "n"(NMax) : "memory");
}
__device__ __forceinline__ void ldsm_x4(uint32_t* r, uint32_t addr) {
    asm volatile("ldmatrix.sync.aligned.m8n8.x4.shared.b16 {%0,%1,%2,%3}, [%4];"
        : "=r"(r[0]), "=r"(r[1]), "=r"(r[2]), "=r"(r[3]) : "r"(addr));
}
__device__ __forceinline__ void ldsm_x4_t(uint32_t* r, uint32_t addr) {
    asm volatile("ldmatrix.sync.aligned.m8n8.x4.trans.shared.b16 {%0,%1,%2,%3}, [%4];"
        : "=r"(r[0]), "=r"(r[1]), "=r"(r[2]), "=r"(r[3]) : "r"(addr));
}
__device__ __forceinline__ void mma_fp16(float* c, const uint32_t* a, const uint32_t* b) {
    asm volatile(
        "mma.sync.aligned.m16n8k16.row.col.f32.f16.f16.f32 "
        "{%0,%1,%2,%3}, {%4,%5,%6,%7}, {%8,%9}, {%0,%1,%2,%3};"
        : "+f"(c[0]), "+f"(c[1]), "+f"(c[2]), "+f"(c[3])
        : "r"(a[0]), "r"(a[1]), "r"(a[2]), "r"(a[3]), "r"(b[0]), "r"(b[1]));
}
__device__ __forceinline__ uint32_t pack_h2(float a, float b) {
    __half2 h = __floats2half2_rn(a, b);
    return *(uint32_t*)&h;
}

// ---------------------------------------------------------------------------
// Node 1: transpose_x(+fp16) + W fp16 + pool PARTIALS (128 parallel blocks).
// grid (16, 12, 18): z<16 transpose slices; z==16 W; z==17 pooling partials.
// ---------------------------------------------------------------------------
__global__ void convert_kernel(const float* __restrict__ x,
                               const float* __restrict__ W) {
    if (blockIdx.z == 16) {
        int tid = (blockIdx.y * 16 + blockIdx.x) * 256 +
                  threadIdx.y * 32 + threadIdx.x;
        for (int i = tid; i < C_ * C_; i += 192 * 256)
            g_W16[i] = __float2half_rn(W[i]);
        return;
    }
    if (blockIdx.z == 17) {
        int blk = blockIdx.y * 16 + blockIdx.x;       // 0..191
        if (blk >= B_ * 8) return;
        int b = blk >> 3, seg = blk & 7;
        int t = threadIdx.y * 32 + threadIdx.x;       // 0..255
        const float* xb = x + (size_t)b * N_ * C_ + (size_t)seg * 64 * C_;
        for (int c = t; c < C_; c += 256) {
            float s = 0.f;
            #pragma unroll 8
            for (int n = 0; n < 64; n++) s += xb[(size_t)n * C_ + c];
            g_qpart[b][seg][c] = s;
        }
        return;
    }
    __shared__ float tbuf[32][33];
    int b = blockIdx.z;
    int n0 = blockIdx.x * 32, c0 = blockIdx.y * 32;
    int tx = threadIdx.x, ty = threadIdx.y;   // 32 x 8
    #pragma unroll
    for (int i = 0; i < 4; i++)
        tbuf[ty + i * 8][tx] = x[(size_t)b * N_ * C_ + (size_t)(n0 + ty + i * 8) * C_ + c0 + tx];
    __syncthreads();
    #pragma unroll
    for (int i = 0; i < 4; i++) {
        float v = tbuf[tx][ty + i * 8];
        size_t o = (size_t)b * C_ * N_ + (size_t)(c0 + ty + i * 8) * N_ + n0 + tx;
        g_xT16[o] = __float2half_rn(v);
    }
}

// ---------------------------------------------------------------------------
// Node 2: finish pool + normalize + logits + softmax -> g_attn (tiny)
// ---------------------------------------------------------------------------
__global__ void attn_kernel(const float* __restrict__ centers) {
    int b = blockIdx.x;
    int tid = threadIdx.x;
    __shared__ float s_q[C_];
    __shared__ float s_red[C_];
    __shared__ float s_logit[K_];
    __shared__ float s_mx, s_den;

    float sum = 0.f;
    #pragma unroll
    for (int seg = 0; seg < 8; seg++) sum += g_qpart[b][seg][tid];
    s_q[tid] = sum * (1.0f / N_);
    __syncthreads();

    float v = s_q[tid];
    s_red[tid] = v * v;
    __syncthreads();
    if (tid < 128) s_red[tid] += s_red[tid + 128] + s_red[tid + 256];
    __syncthreads();
    for (int s = 64; s > 0; s >>= 1) {
        if (tid < s) s_red[tid] += s_red[tid + s];
        __syncthreads();
    }
    float qnorm = sqrtf(s_red[0]);

    if (tid < K_) {
        float dot = 0.f, cs = 0.f;
        #pragma unroll 4
        for (int c = 0; c < C_; c++) {
            float w = centers[(size_t)c * K_ + tid];
            dot += s_q[c] * w;
            cs  += w * w;
        }
        float denom = fmaxf(qnorm, 1e-12f) * fmaxf(sqrtf(cs), 1e-12f);
        s_logit[tid] = dot / denom;
    }
    __syncthreads();

    if (tid == 0) {
        float mx = -1e30f;
        for (int k = 0; k < K_; k++) mx = fmaxf(mx, s_logit[k]);
        float den = 0.f;
        for (int k = 0; k < K_; k++) den += expf(s_logit[k] - mx);
        s_mx = mx; s_den = den;
    }
    __syncthreads();
    if (tid < K_) g_attn[b * K_ + tid] = expf(s_logit[tid] - s_mx) / s_den;
}

// ---------------------------------------------------------------------------
// Node 3: tm via tensor cores + resets g_flag for node 4.
// ---------------------------------------------------------------------------
__global__ __launch_bounds__(256)
void tm_tc_kernel(const float* __restrict__ tran) {
    __shared__ __align__(16) __half s_tr[64 * 128];   // 16KB, swizzled
    __shared__ __align__(16) __half s_at[16 * 64];    // 2KB,  swizzled

    const int tid = threadIdx.x;
    const int warp = tid >> 5, lane = tid & 31;
    const int g = lane >> 2, t4 = lane & 3;
    const int nm0 = blockIdx.x * 128;

    if (blockIdx.x == 0 && tid < 64) g_flag[tid] = 0;   // reset for node 4

    {
        int b = tid >> 4, kq = tid & 15;
        float4 av = *(const float4*)(g_attn + b * 64 + kq * 4);
        uint2 hv;
        hv.x = pack_h2(av.x, av.y);
        hv.y = pack_h2(av.z, av.w);
        int chunk = kq >> 1;
        int base = b * 64 + ((chunk ^ (b & 7)) << 3) + (kq & 1) * 4;
        *(uint2*)(s_at + base) = hv;
    }

    #pragma unroll
    for (int i = 0; i < 8; i++) {
        int f = tid + 256 * i;
        int k = f >> 5, c4 = f & 31;
        float4 v = *(const float4*)(tran + (size_t)k * NN_ + nm0 + c4 * 4);
        uint2 hv;
        hv.x = pack_h2(v.x, v.y);
        hv.y = pack_h2(v.z, v.w);
        int chunk = c4 >> 1;
        int base = k * 128 + ((chunk ^ (k & 7)) << 3) + (c4 & 1) * 4;
        *(uint2*)(s_tr + base) = hv;
    }
    __syncthreads();

    const uint32_t at_base = smem_u32(s_at);
    uint32_t a[4][4];
    {
        int sub = lane >> 3;
        int br = ((sub & 1) << 3) + (lane & 7);
        #pragma unroll
        for (int kc = 0; kc < 4; kc++) {
            int ch16 = kc * 2 + (sub >> 1);
            uint32_t ad = at_base + br * 128 + ((ch16 ^ (br & 7)) << 4);
            ldsm_x4(a[kc], ad);
        }
    }

    const uint32_t tr_base = smem_u32(s_tr);
    float acc[2][4] = {{0.f,0.f,0.f,0.f},{0.f,0.f,0.f,0.f}};
    {
        int sub = lane >> 3;
        int krow_off = ((sub & 1) << 3) + (lane & 7);
        int nch8 = warp * 2 + (sub >> 1);
        #pragma unroll
        for (int kc = 0; kc < 4; kc++) {
            int k = kc * 16 + krow_off;
            uint32_t bd = tr_base + k * 256 + ((nch8 ^ (k & 7)) << 4);
            uint32_t bt[4];
            ldsm_x4_t(bt, bd);
            mma_fp16(acc[0], a[kc], &bt[0]);
            mma_fp16(acc[1], a[kc], &bt[2]);
        }
    }

    uint32_t* out = (uint32_t*)g_tm16;
    #pragma unroll
    for (int n8 = 0; n8 < 2; n8++) {
        int col = nm0 + warp * 16 + n8 * 8 + 2 * t4;
        out[((size_t)g * NN_ + col) >> 1]       = pack_h2(acc[n8][0], acc[n8][1]);
        out[((size_t)(g + 8) * NN_ + col) >> 1] = pack_h2(acc[n8][2], acc[n8][3]);
    }
}

// ---------------------------------------------------------------------------
// fp16 GEMM body (shared by both halves of the fused node).
// CTA 128x64x32, 8 warps (4m x 2n), warp tile 32x32, 3-stage cp.async.
// ---------------------------------------------------------------------------
#define TBM 128
#define TBN 64
#define TBK 32
#define A_BYTES (TBM*TBK*2)            // 8192
#define B_BYTES (TBN*TBK*2)            // 4096
#define STAGE_BYTES (A_BYTES + B_BYTES)        // 12288
#define NSTAGE 3
#define GSMEM_BYTES (NSTAGE*STAGE_BYTES)       // 36864

template <int EPI>
__device__ __forceinline__ void gemm_body(
    uint32_t smb,
    const __half* __restrict__ Ab, const __half* __restrict__ Bb,
    float* __restrict__ Cf, __half* __restrict__ Ch,
    const float* __restrict__ bias,
    int Kk, int lda, int ldb, int ldc,
    int m0, int n0, size_t cbase) {

    const int tid = threadIdx.x;
    const int warp = tid >> 5, lane = tid & 31;
    const int wm = warp >> 1, wn = warp & 1;
    const int g = lane >> 2, t4 = lane & 3;

    auto issue_copy = [&](int s, int k0) {
        uint32_t st = smb + (uint32_t)s * STAGE_BYTES;
        #pragma unroll
        for (int i = 0; i < 2; i++) {
            int id = tid + 256 * i;
            int r = id >> 2, c = id & 3;
            uint32_t d = st + (uint32_t)(r * 64 + ((c ^ ((r >> 1) & 3)) << 4));
            cp_async16(d, Ab + (size_t)(m0 + r) * lda + k0 + c * 8);
        }
        {
            uint32_t bst = st + A_BYTES;
            int r = tid >> 2, c = tid & 3;
            uint32_t d = bst + (uint32_t)(r * 64 + ((c ^ ((r >> 1) & 3)) << 4));
            cp_async16(d, Bb + (size_t)(n0 + r) * ldb + k0 + c * 8);
        }
    };

    float acc[2][4][4];
    #pragma unroll
    for (int mt = 0; mt < 2; mt++)
        #pragma unroll
        for (int nt = 0; nt < 4; nt++)
            #pragma unroll
            for (int q = 0; q < 4; q++) acc[mt][nt][q] = 0.f;

    const int lrA = lane & 15, lkA = (lane >> 4) & 1;
    int offA[2], qA[2];
    #pragma unroll
    for (int mt = 0; mt < 2; mt++) {
        int r = wm * 32 + mt * 16 + lrA;
        offA[mt] = r * 64;
        qA[mt] = (r >> 1) & 3;
    }
    const int b_ntloc = (lane >> 4) & 1, b_kh = (lane >> 3) & 1;
    int offB[2], qB[2];
    #pragma unroll
    for (int P = 0; P < 2; P++) {
        int r = wn * 32 + P * 16 + b_ntloc * 8 + (lane & 7);
        offB[P] = r * 64;
        qB[P] = (r >> 1) & 3;
    }

    auto compute = [&](int s) {
        uint32_t st = smb + (uint32_t)s * STAGE_BYTES;
        uint32_t bst = st + A_BYTES;
        #pragma unroll
        for (int ks = 0; ks < 2; ks++) {
            uint32_t ah[2][4], bh[2][4];
            #pragma unroll
            for (int mt = 0; mt < 2; mt++)
                ldsm_x4(ah[mt], st + offA[mt] + ((((ks * 2 + lkA) ^ qA[mt])) << 4));
            #pragma unroll
            for (int P = 0; P < 2; P++)
                ldsm_x4(bh[P], bst + offB[P] + ((((ks * 2 + b_kh) ^ qB[P])) << 4));
            #pragma unroll
            for (int mt = 0; mt < 2; mt++)
                #pragma unroll
                for (int nt = 0; nt < 4; nt++)
                    mma_fp16(acc[mt][nt], ah[mt], &bh[nt >> 1][(nt & 1) * 2]);
        }
    };

    const int nch = Kk / TBK;

    #pragma unroll
    for (int p = 0; p < NSTAGE - 1; p++) {
        if (p < nch) issue_copy(p, p * TBK);
        cp_commit();
    }

    for (int ch = 0; ch < nch; ch++) {
        cp_wait<NSTAGE - 2>();
        __syncthreads();
        int nxt = ch + NSTAGE - 1;
        if (nxt < nch) issue_copy(nxt % NSTAGE, nxt * TBK);
        cp_commit();
        compute(ch % NSTAGE);
    }

    #pragma unroll
    for (int mt = 0; mt < 2; mt++) {
        int r0 = m0 + wm * 32 + mt * 16 + g;
        #pragma unroll
        for (int nt = 0; nt < 4; nt++) {
            int col = n0 + wn * 32 + nt * 8 + t4 * 2;
            if (EPI == 0) {
                uint32_t* chp = (uint32_t*)Ch;
                chp[(cbase + (size_t)r0 * ldc + col) >> 1] =
                    pack_h2(acc[mt][nt][0], acc[mt][nt][1]);
                chp[(cbase + (size_t)(r0 + 8) * ldc + col) >> 1] =
                    pack_h2(acc[mt][nt][2], acc[mt][nt][3]);
            } else {
                float b0 = __ldg(bias + col), b1 = __ldg(bias + col + 1);
                float* p0 = Cf + (size_t)r0 * ldc + col;
                float* p1 = Cf + (size_t)(r0 + 8) * ldc + col;
                *(float2*)p0 = make_float2(acc[mt][nt][0] + b0, acc[mt][nt][1] + b1);
                *(float2*)p1 = make_float2(acc[mt][nt][2] + b0, acc[mt][nt][3] + b1);
            }
        }
    }
}

// ---------------------------------------------------------------------------
// Node 4: fused gemm1 + gemm2 with device-side dependency flags.
// blocks 0..383  : gemm1 tiles (y = tm @ x), signal g_flag[b*4+mt]
// blocks 384..767: gemm2 tiles (out = y @ W^T + b), spin on g_flag[rb]==6
// ---------------------------------------------------------------------------
__global__ __launch_bounds__(256, 3)
void gemm_fused(const __half* __restrict__ tm16, const __half* __restrict__ xt16,
                __half* __restrict__ y16, const __half* __restrict__ w16,
                float* __restrict__ out, const float* __restrict__ bias) {
    extern __shared__ char sm[];
    const uint32_t smb = smem_u32(sm);
    const int bid = blockIdx.x;

    if (bid < 384) {
        // gemm1: id = mt + 4*(ct + 6*b)
        int mt = bid & 3;
        int tmp = bid >> 2;
        int ct = tmp % 6, b = tmp / 6;
        int m0 = mt * 128, n0 = ct * 64;
        gemm_body<0>(smb,
                     tm16 + (size_t)b * NN_, xt16 + (size_t)b * C_ * N_,
                     nullptr, y16, nullptr,
                     /*K=*/N_, /*lda=*/N_, /*ldb=*/N_, /*ldc=*/C_,
                     m0, n0, (size_t)b * N_ * C_);
        __syncthreads();
        __threadfence();
        if (threadIdx.x == 0) atomicAdd(&g_flag[b * 4 + mt], 1);
    } else {
        // gemm2: id2 = rb + 64*ct
        int id2 = bid - 384;
        int rb = id2 & 63, ct = id2 >> 6;
        int m0 = rb * 128, n0 = ct * 64;
        if (threadIdx.x == 0) {
            while (((volatile int*)g_flag)[rb] < 6) {}
            __threadfence();
        }
        __syncthreads();
        gemm_body<1>(smb,
                     y16, w16, out, nullptr, bias,
                     /*K=*/C_, /*lda=*/C_, /*ldb=*/C_, /*ldc=*/C_,
                     m0, n0, 0);
    }
}

// ---------------------------------------------------------------------------
extern "C" void kernel_launch(void* const* d_in, const int* in_sizes, int n_in,
                              void* d_out, int out_size) {
    const float* x       = (const float*)d_in[0];  // [B,N,C]
    const float* centers = (const float*)d_in[1];  // [C,K]
    const float* tran_ms = (const float*)d_in[2];  // [K,N,N]
    const float* proj_w  = (const float*)d_in[3];  // [C,C]
    const float* proj_b  = (const float*)d_in[4];  // [C]
    float* out = (float*)d_out;                    // [B,N,C]

    __half *tm16, *xt16, *y16, *w16;
    cudaGetSymbolAddress((void**)&tm16, g_tm16);
    cudaGetSymbolAddress((void**)&xt16, g_xT16);
    cudaGetSymbolAddress((void**)&y16, g_y16);
    cudaGetSymbolAddress((void**)&w16, g_W16);

    cudaFuncSetAttribute(gemm_fused, cudaFuncAttributeMaxDynamicSharedMemorySize,
                         GSMEM_BYTES);

    // Node 1: transpose + W conversion + pool partials (128 parallel blocks)
    convert_kernel<<<dim3(N_/32, C_/32, B_ + 2), dim3(32, 8)>>>(x, proj_w);

    // Node 2: routing weights (tiny)
    attn_kernel<<<B_, C_>>>(centers);

    // Node 3: tm = attn @ tran_ms via tensor cores (also resets g_flag)
    tm_tc_kernel<<<NN_ / 128, 256>>>(tran_ms);

    // Node 4 (ncu capture slot): gemm1 + gemm2 fused (flag-synchronized)
    gemm_fused<<<768, 256, GSMEM_BYTES>>>(tm16, xt16, y16, w16, out, proj_b);
}